// round 1
// baseline (speedup 1.0000x reference)
#include <cuda_runtime.h>

#define HH 1024
#define WW 1536
#define NN (HH*WW)

// ---------------- device scratch (no allocation allowed) ----------------
static __device__ int g_dst[NN];                // per-pixel destination id
static __device__ int g_y1[NN];                 // scatter pass 1 / reused: colsum / d4
static __device__ int g_y2[NN];                 // scatter pass 2 / reused: d8
static __device__ unsigned char g_m0[NN];       // pre-erosion mask
static __device__ unsigned char g_mask[NN];     // eroded mask
static __device__ int g_labA[NN];               // label ping
static __device__ int g_labB[NN];               // label pong
static __device__ int g_d2[NN];                 // dst composed twice
static __device__ int g_cnt[NN + 1];            // per-label size
static __device__ int g_labi[NN];               // final per-pixel label

// ---------------- kernels ----------------

// dst_ids: unit displacement * clipped length, clip to image, round-half-even
__global__ void k_dst(const float* __restrict__ df) {
    int i = blockIdx.x * blockDim.x + threadIdx.x;
    if (i >= NN) return;
    float dx = df[i];
    float dy = df[NN + i];
    // avoid fma-contraction so we mirror XLA's unfused elementwise ops
    float l2  = __fadd_rn(__fmul_rn(dx, dx), __fmul_rn(dy, dy));
    float len = __fsqrt_rn(l2);
    float den = __fadd_rn(len, 1e-19f);
    float ux  = __fdiv_rn(dx, den);
    float uy  = __fdiv_rn(dy, den);
    float dfc = fminf(fmaxf(len, 3.0f), 6.0f);
    int r = i / WW;
    int c = i - r * WW;
    float px = __fadd_rn((float)r, __fmul_rn(ux, dfc));
    float py = __fadd_rn((float)c, __fmul_rn(uy, dfc));
    px = fminf(fmaxf(px, 0.0f), (float)(HH - 1));
    py = fminf(fmaxf(py, 0.0f), (float)(WW - 1));
    int ri = __float2int_rn(px);   // cvt.rni: round to nearest, ties to even (matches jnp.round)
    int ci = __float2int_rn(py);
    g_dst[i] = ri * WW + ci;
}

// y1[dst[i]] += fore[i]
__global__ void k_scat1(const float* __restrict__ yh) {
    int i = blockIdx.x * blockDim.x + threadIdx.x;
    if (i >= NN) return;
    if (yh[i] > 0.5f) atomicAdd(&g_y1[g_dst[i]], 1);
}

// y2[dst[i]] += y1[i]
__global__ void k_scat2() {
    int i = blockIdx.x * blockDim.x + threadIdx.x;
    if (i >= NN) return;
    int v = g_y1[i];
    if (v) atomicAdd(&g_y2[g_dst[i]], v);
}

// vertical 5-sum of y2 -> g_y1 (reuse)
__global__ void k_colsum() {
    int i = blockIdx.x * blockDim.x + threadIdx.x;
    if (i >= NN) return;
    int r = i / WW;
    int s = 0;
#pragma unroll
    for (int dr = -2; dr <= 2; dr++) {
        int rr = r + dr;
        if (rr >= 0 && rr < HH) s += g_y2[i + dr * WW];
    }
    g_y1[i] = s;
}

// horizontal 5-sum + exact integer threshold  (ya >= 0.5  <=>  2*s >= count)
__global__ void k_pool_thresh() {
    int i = blockIdx.x * blockDim.x + threadIdx.x;
    if (i >= NN) return;
    int r = i / WW;
    int c = i - r * WW;
    int s = 0;
#pragma unroll
    for (int dc = -2; dc <= 2; dc++) {
        int cc = c + dc;
        if (cc >= 0 && cc < WW) s += g_y1[i + dc];
    }
    int rin = min(r + 2, HH - 1) - max(r - 2, 0) + 1;
    int cin = min(c + 2, WW - 1) - max(c - 2, 0) + 1;
    g_m0[i] = (unsigned char)(2 * s >= rin * cin);
}

// 3x3-cross erosion with border treated as foreground; init labels
__global__ void k_erode_init() {
    int i = blockIdx.x * blockDim.x + threadIdx.x;
    if (i >= NN) return;
    int r = i / WW;
    int c = i - r * WW;
    unsigned char m = g_m0[i];
    if (m) {
        if (r > 0      && !g_m0[i - WW]) m = 0;
        if (m && r < HH - 1 && !g_m0[i + WW]) m = 0;
        if (m && c > 0      && !g_m0[i - 1])  m = 0;
        if (m && c < WW - 1 && !g_m0[i + 1])  m = 0;
    }
    g_mask[i] = m;
    g_labA[i] = m ? (i + 1) : 0;
}

// one masked 3x3 max-dilation step, 4 pixels/thread (int4), separable row-max
__global__ void k_dilate(const int* __restrict__ src, int* __restrict__ dst) {
    int q = blockIdx.x * blockDim.x + threadIdx.x;   // column quad [0, WW/4)
    int r = blockIdx.y * blockDim.y + threadIdx.y;   // row
    int c = q * 4;
    int base = r * WW + c;
    int m0x = 0, m0y = 0, m0z = 0, m0w = 0;
    int m1x = 0, m1y = 0, m1z = 0, m1w = 0;
    int m2x = 0, m2y = 0, m2z = 0, m2w = 0;
#pragma unroll
    for (int k = 0; k < 3; k++) {
        int rr = r - 1 + k;
        int rx = 0, ry = 0, rz = 0, rw = 0;
        if (rr >= 0 && rr < HH) {
            const int* p = src + rr * WW + c;
            int4 v = *(const int4*)p;
            int L = (c > 0)       ? p[-1] : 0;
            int R = (c + 4 < WW)  ? p[4]  : 0;
            int a = max(v.x, v.y);
            int b = max(v.y, v.z);
            int t = max(v.z, v.w);
            rx = max(L, a);
            ry = max(a, v.z);
            rz = max(b, v.w);
            rw = max(t, R);
        }
        if (k == 0) { m0x = rx; m0y = ry; m0z = rz; m0w = rw; }
        else if (k == 1) { m1x = rx; m1y = ry; m1z = rz; m1w = rw; }
        else { m2x = rx; m2y = ry; m2z = rz; m2w = rw; }
    }
    uchar4 mk = *(const uchar4*)&g_mask[base];
    int4 o;
    o.x = mk.x ? max(m0x, max(m1x, m2x)) : 0;
    o.y = mk.y ? max(m0y, max(m1y, m2y)) : 0;
    o.z = mk.z ? max(m0z, max(m1z, m2z)) : 0;
    o.w = mk.w ? max(m0w, max(m1w, m2w)) : 0;
    *(int4*)&dst[base] = o;
}

// out[i] = map[map[i]]  (pointer doubling of the dst function)
__global__ void k_compose(const int* __restrict__ mp, int* __restrict__ out) {
    int i = blockIdx.x * blockDim.x + threadIdx.x;
    if (i >= NN) return;
    out[i] = mp[mp[i]];
}

// lab_i = fore ? lab[d8[i]] : 0 ; histogram per label
__global__ void k_labi(const float* __restrict__ yh) {
    int i = blockIdx.x * blockDim.x + threadIdx.x;
    if (i >= NN) return;
    int la = 0;
    if (yh[i] > 0.5f) la = g_labA[g_y2[i]];   // g_y2 holds d8 here
    g_labi[i] = la;
    if (la > 0) atomicAdd(&g_cnt[la], 1);
}

// keep components with size > 256; value = label (inst_m[L] == L exactly)
__global__ void k_final(float* __restrict__ out) {
    int i = blockIdx.x * blockDim.x + threadIdx.x;
    if (i >= NN) return;
    int la = g_labi[i];
    out[i] = (la > 0 && g_cnt[la] > 256) ? (float)la : 0.0f;
}

// ---------------- launcher ----------------
extern "C" void kernel_launch(void* const* d_in, const int* in_sizes, int n_in,
                              void* d_out, int out_size) {
    const float* y_hat;
    const float* df;
    if (in_sizes[0] == NN) { y_hat = (const float*)d_in[0]; df = (const float*)d_in[1]; }
    else                   { df = (const float*)d_in[0]; y_hat = (const float*)d_in[1]; }
    float* out = (float*)d_out;

    void *py1, *py2, *pcnt, *pA, *pB, *pd2;
    cudaGetSymbolAddress(&py1, g_y1);
    cudaGetSymbolAddress(&py2, g_y2);
    cudaGetSymbolAddress(&pcnt, g_cnt);
    cudaGetSymbolAddress(&pA, g_labA);
    cudaGetSymbolAddress(&pB, g_labB);
    cudaGetSymbolAddress(&pd2, g_d2);

    cudaMemsetAsync(py1, 0, (size_t)NN * 4, 0);
    cudaMemsetAsync(py2, 0, (size_t)NN * 4, 0);
    cudaMemsetAsync(pcnt, 0, (size_t)(NN + 1) * 4, 0);

    const int B = 256;
    const int G = (NN + B - 1) / B;

    k_dst<<<G, B>>>(df);
    k_scat1<<<G, B>>>(y_hat);
    k_scat2<<<G, B>>>();
    k_colsum<<<G, B>>>();
    k_pool_thresh<<<G, B>>>();
    k_erode_init<<<G, B>>>();

    // pointer doubling: d2 -> g_d2, d4 -> g_y1, d8 -> g_y2
    {
        void* pdst; cudaGetSymbolAddress(&pdst, g_dst);
        k_compose<<<G, B>>>((const int*)pdst, (int*)pd2);
        k_compose<<<G, B>>>((const int*)pd2, (int*)py1);
        k_compose<<<G, B>>>((const int*)py1, (int*)py2);
    }

    // exactly 300 masked max-dilations (idempotent past convergence, so this
    // matches the while_loop regardless of where it actually converges)
    dim3 blk(32, 8);
    dim3 grd((WW / 4) / 32, HH / 8);
    int* a = (int*)pA;
    int* b = (int*)pB;
    for (int it = 0; it < 300; it++) {
        k_dilate<<<grd, blk>>>(a, b);
        int* t = a; a = b; b = t;
    }
    // 300 is even -> result back in g_labA

    k_labi<<<G, B>>>(y_hat);
    k_final<<<G, B>>>(out);
}

// round 2
// speedup vs baseline: 11.0338x; 11.0338x over previous
#include <cuda_runtime.h>

#define HH 1024
#define WW 1536
#define NN (HH*WW)

// ---------------- device scratch (no allocation allowed) ----------------
static __device__ int g_dst[NN];                // per-pixel destination id
static __device__ int g_y1[NN];                 // scatter pass 1 / reused: colsum / d4
static __device__ int g_y2[NN];                 // scatter pass 2 / reused: d8
static __device__ unsigned char g_m0[NN];       // pre-erosion mask
static __device__ unsigned char g_mask[NN];     // eroded mask
static __device__ int g_labA[NN];               // final labels (root+1)
static __device__ int g_par[NN];                // union-find parent
static __device__ int g_d2[NN];                 // dst composed twice
static __device__ int g_cnt[NN + 1];            // per-label size
static __device__ int g_labi[NN];               // final per-pixel label

// ---------------- kernels ----------------

// dst_ids: unit displacement * clipped length, clip to image, round-half-even
__global__ void k_dst(const float* __restrict__ df) {
    int i = blockIdx.x * blockDim.x + threadIdx.x;
    if (i >= NN) return;
    float dx = df[i];
    float dy = df[NN + i];
    float l2  = __fadd_rn(__fmul_rn(dx, dx), __fmul_rn(dy, dy));
    float len = __fsqrt_rn(l2);
    float den = __fadd_rn(len, 1e-19f);
    float ux  = __fdiv_rn(dx, den);
    float uy  = __fdiv_rn(dy, den);
    float dfc = fminf(fmaxf(len, 3.0f), 6.0f);
    int r = i / WW;
    int c = i - r * WW;
    float px = __fadd_rn((float)r, __fmul_rn(ux, dfc));
    float py = __fadd_rn((float)c, __fmul_rn(uy, dfc));
    px = fminf(fmaxf(px, 0.0f), (float)(HH - 1));
    py = fminf(fmaxf(py, 0.0f), (float)(WW - 1));
    int ri = __float2int_rn(px);   // ties-to-even, matches jnp.round
    int ci = __float2int_rn(py);
    g_dst[i] = ri * WW + ci;
}

// y1[dst[i]] += fore[i]
__global__ void k_scat1(const float* __restrict__ yh) {
    int i = blockIdx.x * blockDim.x + threadIdx.x;
    if (i >= NN) return;
    if (yh[i] > 0.5f) atomicAdd(&g_y1[g_dst[i]], 1);
}

// y2[dst[i]] += y1[i]
__global__ void k_scat2() {
    int i = blockIdx.x * blockDim.x + threadIdx.x;
    if (i >= NN) return;
    int v = g_y1[i];
    if (v) atomicAdd(&g_y2[g_dst[i]], v);
}

// vertical 5-sum of y2 -> g_y1 (reuse)
__global__ void k_colsum() {
    int i = blockIdx.x * blockDim.x + threadIdx.x;
    if (i >= NN) return;
    int r = i / WW;
    int s = 0;
#pragma unroll
    for (int dr = -2; dr <= 2; dr++) {
        int rr = r + dr;
        if (rr >= 0 && rr < HH) s += g_y2[i + dr * WW];
    }
    g_y1[i] = s;
}

// horizontal 5-sum + exact integer threshold  (ya >= 0.5  <=>  2*s >= count)
__global__ void k_pool_thresh() {
    int i = blockIdx.x * blockDim.x + threadIdx.x;
    if (i >= NN) return;
    int r = i / WW;
    int c = i - r * WW;
    int s = 0;
#pragma unroll
    for (int dc = -2; dc <= 2; dc++) {
        int cc = c + dc;
        if (cc >= 0 && cc < WW) s += g_y1[i + dc];
    }
    int rin = min(r + 2, HH - 1) - max(r - 2, 0) + 1;
    int cin = min(c + 2, WW - 1) - max(c - 2, 0) + 1;
    g_m0[i] = (unsigned char)(2 * s >= rin * cin);
}

// 3x3-cross erosion (border = foreground); init union-find parents
__global__ void k_erode_init() {
    int i = blockIdx.x * blockDim.x + threadIdx.x;
    if (i >= NN) return;
    int r = i / WW;
    int c = i - r * WW;
    unsigned char m = g_m0[i];
    if (m) {
        if (r > 0      && !g_m0[i - WW]) m = 0;
        if (m && r < HH - 1 && !g_m0[i + WW]) m = 0;
        if (m && c > 0      && !g_m0[i - 1])  m = 0;
        if (m && c < WW - 1 && !g_m0[i + 1])  m = 0;
    }
    g_mask[i] = m;
    g_par[i] = i;           // self-parent (also for non-mask; unused there)
}

__device__ __forceinline__ int uf_find(int i) {
    int p = g_par[i];
    while (p != g_par[p]) p = g_par[p];
    return p;
}

// lock-free union: hook the SMALLER root under the LARGER root.
// Final root of each component == max linear index in it (reference's label).
__device__ void uf_union(int a, int b) {
    while (true) {
        a = uf_find(a);
        b = uf_find(b);
        if (a == b) return;
        int hi = max(a, b);
        int lo = min(a, b);
        int old = atomicCAS(&g_par[lo], lo, hi);
        if (old == lo) return;      // hooked successfully
        a = hi; b = old;            // lo's root moved; retry from there
    }
}

// union each mask pixel with its E, SW, S, SE mask neighbors (covers 8-conn)
__global__ void k_union() {
    int i = blockIdx.x * blockDim.x + threadIdx.x;
    if (i >= NN) return;
    if (!g_mask[i]) return;
    int r = i / WW;
    int c = i - r * WW;
    if (c < WW - 1 && g_mask[i + 1]) uf_union(i, i + 1);
    if (r < HH - 1) {
        if (g_mask[i + WW]) uf_union(i, i + WW);
        if (c > 0      && g_mask[i + WW - 1]) uf_union(i, i + WW - 1);
        if (c < WW - 1 && g_mask[i + WW + 1]) uf_union(i, i + WW + 1);
    }
}

// flatten: labels = root+1 on mask, 0 elsewhere (roots are stable now)
__global__ void k_flatten() {
    int i = blockIdx.x * blockDim.x + threadIdx.x;
    if (i >= NN) return;
    g_labA[i] = g_mask[i] ? (uf_find(i) + 1) : 0;
}

// out[i] = map[map[i]]  (pointer doubling of the dst function)
__global__ void k_compose(const int* __restrict__ mp, int* __restrict__ out) {
    int i = blockIdx.x * blockDim.x + threadIdx.x;
    if (i >= NN) return;
    out[i] = mp[mp[i]];
}

// lab_i = fore ? lab[d8[i]] : 0 ; histogram per label
__global__ void k_labi(const float* __restrict__ yh) {
    int i = blockIdx.x * blockDim.x + threadIdx.x;
    if (i >= NN) return;
    int la = 0;
    if (yh[i] > 0.5f) la = g_labA[g_y2[i]];   // g_y2 holds d8 here
    g_labi[i] = la;
    if (la > 0) atomicAdd(&g_cnt[la], 1);
}

// keep components with size > 256; value = label (inst_m[L] == L exactly)
__global__ void k_final(float* __restrict__ out) {
    int i = blockIdx.x * blockDim.x + threadIdx.x;
    if (i >= NN) return;
    int la = g_labi[i];
    out[i] = (la > 0 && g_cnt[la] > 256) ? (float)la : 0.0f;
}

// ---------------- launcher ----------------
extern "C" void kernel_launch(void* const* d_in, const int* in_sizes, int n_in,
                              void* d_out, int out_size) {
    const float* y_hat;
    const float* df;
    if (in_sizes[0] == NN) { y_hat = (const float*)d_in[0]; df = (const float*)d_in[1]; }
    else                   { df = (const float*)d_in[0]; y_hat = (const float*)d_in[1]; }
    float* out = (float*)d_out;

    void *py1, *py2, *pcnt, *pd2, *pdst;
    cudaGetSymbolAddress(&py1, g_y1);
    cudaGetSymbolAddress(&py2, g_y2);
    cudaGetSymbolAddress(&pcnt, g_cnt);
    cudaGetSymbolAddress(&pd2, g_d2);
    cudaGetSymbolAddress(&pdst, g_dst);

    cudaMemsetAsync(py1, 0, (size_t)NN * 4, 0);
    cudaMemsetAsync(py2, 0, (size_t)NN * 4, 0);
    cudaMemsetAsync(pcnt, 0, (size_t)(NN + 1) * 4, 0);

    const int B = 256;
    const int G = (NN + B - 1) / B;

    k_dst<<<G, B>>>(df);
    k_scat1<<<G, B>>>(y_hat);
    k_scat2<<<G, B>>>();
    k_colsum<<<G, B>>>();
    k_pool_thresh<<<G, B>>>();
    k_erode_init<<<G, B>>>();

    // connected components via lock-free union-find (replaces 300 dilations;
    // valid iff the reference's while-loop converged before its 300-iter cap)
    k_union<<<G, B>>>();
    k_flatten<<<G, B>>>();

    // pointer doubling: d2 -> g_d2, d4 -> g_y1, d8 -> g_y2
    k_compose<<<G, B>>>((const int*)pdst, (int*)pd2);
    k_compose<<<G, B>>>((const int*)pd2, (int*)py1);
    k_compose<<<G, B>>>((const int*)py1, (int*)py2);

    k_labi<<<G, B>>>(y_hat);
    k_final<<<G, B>>>(out);
}

// round 4
// speedup vs baseline: 13.2892x; 1.2044x over previous
#include <cuda_runtime.h>

#define HH 1024
#define WW 1536
#define NN (HH*WW)

// ---------------- device scratch (no allocation allowed) ----------------
// pooled zero-init region: [0,NN)=y1 ; [NN,2NN)=y2 ; [2NN,3NN+1)=cnt
static __device__ int g_pool[3 * NN + 1];
static __device__ int g_dst[NN];
static __device__ unsigned char g_mask[NN];
static __device__ int g_par[NN];
static __device__ int g_lab[NN];
static __device__ int g_labi[NN];

// ---------------- kernels ----------------

// dst_ids + first scatter fused
__global__ void k_dst_scat1(const float* __restrict__ yh, const float* __restrict__ df,
                            int* __restrict__ dst, int* __restrict__ y1) {
    int i = blockIdx.x * blockDim.x + threadIdx.x;
    if (i >= NN) return;
    float dx = df[i];
    float dy = df[NN + i];
    float l2  = __fadd_rn(__fmul_rn(dx, dx), __fmul_rn(dy, dy));
    float len = __fsqrt_rn(l2);
    float den = __fadd_rn(len, 1e-19f);
    float ux  = __fdiv_rn(dx, den);
    float uy  = __fdiv_rn(dy, den);
    float dfc = fminf(fmaxf(len, 3.0f), 6.0f);
    int r = i / WW;
    int c = i - r * WW;
    float px = __fadd_rn((float)r, __fmul_rn(ux, dfc));
    float py = __fadd_rn((float)c, __fmul_rn(uy, dfc));
    px = fminf(fmaxf(px, 0.0f), (float)(HH - 1));
    py = fminf(fmaxf(py, 0.0f), (float)(WW - 1));
    int d = __float2int_rn(px) * WW + __float2int_rn(py);  // ties-to-even
    dst[i] = d;
    if (yh[i] > 0.5f) atomicAdd(&y1[d], 1);
}

// y2[dst[i]] += y1[i]
__global__ void k_scat2(const int* __restrict__ dst, const int* __restrict__ y1,
                        int* __restrict__ y2) {
    int i = blockIdx.x * blockDim.x + threadIdx.x;
    if (i >= NN) return;
    int v = y1[i];
    if (v) atomicAdd(&y2[dst[i]], v);
}

// vertical 5-sum, 4 px/thread
__global__ void k_colsum(const int* __restrict__ y2, int* __restrict__ cs) {
    int q = blockIdx.x * blockDim.x + threadIdx.x;
    if (q >= NN / 4) return;
    int i = q * 4;
    int r = i / WW;                       // WW%4==0 -> all 4 in same row
    int4 s = make_int4(0, 0, 0, 0);
#pragma unroll
    for (int dr = -2; dr <= 2; dr++) {
        int rr = r + dr;
        if (rr >= 0 && rr < HH) {
            int4 v = *(const int4*)(y2 + i + dr * WW);
            s.x += v.x; s.y += v.y; s.z += v.z; s.w += v.w;
        }
    }
    *(int4*)(cs + i) = s;
}

// m0 at (r,c) from column sums; exact integer threshold (ya>=0.5 <=> 2s>=cnt)
__device__ __forceinline__ bool m0_at(const int* __restrict__ cs, int r, int c) {
    int s = 0;
#pragma unroll
    for (int dc = -2; dc <= 2; dc++) {
        int cc = c + dc;
        if (cc >= 0 && cc < WW) s += cs[r * WW + cc];
    }
    int rin = min(r + 2, HH - 1) - max(r - 2, 0) + 1;
    int cin = min(c + 2, WW - 1) - max(c - 2, 0) + 1;
    return 2 * s >= rin * cin;
}

// fused: threshold + 3x3-cross erosion (border=foreground) + union-find init
__global__ void k_pool_erode(const int* __restrict__ cs,
                             unsigned char* __restrict__ mask,
                             int* __restrict__ par) {
    int i = blockIdx.x * blockDim.x + threadIdx.x;
    if (i >= NN) return;
    int r = i / WW;
    int c = i - r * WW;
    bool m = m0_at(cs, r, c)
          && (r == 0      || m0_at(cs, r - 1, c))
          && (r == HH - 1 || m0_at(cs, r + 1, c))
          && (c == 0      || m0_at(cs, r, c - 1))
          && (c == WW - 1 || m0_at(cs, r, c + 1));
    mask[i] = (unsigned char)m;
    par[i] = i;
}

__device__ __forceinline__ int uf_find(int* __restrict__ par, int i) {
    int p = par[i];
    while (p != par[p]) p = par[p];
    return p;
}

// lock-free union: hook smaller root under larger root
// -> final root of a component == max linear index (reference's label)
__device__ void uf_union(int* __restrict__ par, int a, int b) {
    while (true) {
        a = uf_find(par, a);
        b = uf_find(par, b);
        if (a == b) return;
        int hi = max(a, b);
        int lo = min(a, b);
        int old = atomicCAS(&par[lo], lo, hi);
        if (old == lo) return;
        a = hi; b = old;
    }
}

// union each mask pixel with E, SW, S, SE mask neighbors (covers 8-conn)
__global__ void k_union(const unsigned char* __restrict__ mask, int* __restrict__ par) {
    int i = blockIdx.x * blockDim.x + threadIdx.x;
    if (i >= NN) return;
    if (!mask[i]) return;
    int r = i / WW;
    int c = i - r * WW;
    if (c < WW - 1 && mask[i + 1]) uf_union(par, i, i + 1);
    if (r < HH - 1) {
        if (mask[i + WW]) uf_union(par, i, i + WW);
        if (c > 0      && mask[i + WW - 1]) uf_union(par, i, i + WW - 1);
        if (c < WW - 1 && mask[i + WW + 1]) uf_union(par, i, i + WW + 1);
    }
}

// labels = root+1 on mask, 0 elsewhere
__global__ void k_flatten(const unsigned char* __restrict__ mask,
                          int* __restrict__ par, int* __restrict__ lab) {
    int i = blockIdx.x * blockDim.x + threadIdx.x;
    if (i >= NN) return;
    lab[i] = mask[i] ? (uf_find(par, i) + 1) : 0;
}

// inst = lab[dst^8(i)] * fore ; per-label histogram.
// dst[j] = j + small displacement -> each hop's gathers are near-coalesced.
__global__ void k_labi(const float* __restrict__ yh, const int* __restrict__ dst,
                       const int* __restrict__ lab, int* __restrict__ labi,
                       int* __restrict__ cnt) {
    int i = blockIdx.x * blockDim.x + threadIdx.x;
    if (i >= NN) return;
    int la = 0;
    if (yh[i] > 0.5f) {
        int j = i;
#pragma unroll
        for (int h = 0; h < 8; h++) j = dst[j];
        la = lab[j];
    }
    labi[i] = la;
    if (la > 0) atomicAdd(&cnt[la], 1);
}

// keep components with size > 256; value = label (segment_max(L)==L exactly)
__global__ void k_final(const int* __restrict__ labi, const int* __restrict__ cnt,
                        float* __restrict__ out) {
    int q = blockIdx.x * blockDim.x + threadIdx.x;
    if (q >= NN / 4) return;
    int i = q * 4;
    int4 la = *(const int4*)(labi + i);
    float4 o;
    o.x = (la.x > 0 && cnt[la.x] > 256) ? (float)la.x : 0.0f;
    o.y = (la.y > 0 && cnt[la.y] > 256) ? (float)la.y : 0.0f;
    o.z = (la.z > 0 && cnt[la.z] > 256) ? (float)la.z : 0.0f;
    o.w = (la.w > 0 && cnt[la.w] > 256) ? (float)la.w : 0.0f;
    *(float4*)(out + i) = o;
}

// ---------------- launcher ----------------
extern "C" void kernel_launch(void* const* d_in, const int* in_sizes, int n_in,
                              void* d_out, int out_size) {
    const float* y_hat;
    const float* df;
    if (in_sizes[0] == NN) { y_hat = (const float*)d_in[0]; df = (const float*)d_in[1]; }
    else                   { df = (const float*)d_in[0]; y_hat = (const float*)d_in[1]; }
    float* out = (float*)d_out;

    void *ppool, *pdst, *pmask, *ppar, *plab, *plabi;
    cudaGetSymbolAddress(&ppool, g_pool);
    cudaGetSymbolAddress(&pdst, g_dst);
    cudaGetSymbolAddress(&pmask, g_mask);
    cudaGetSymbolAddress(&ppar, g_par);
    cudaGetSymbolAddress(&plab, g_lab);
    cudaGetSymbolAddress(&plabi, g_labi);

    int* y1  = (int*)ppool;
    int* y2  = y1 + NN;
    int* cnt = y1 + 2 * NN;

    // one memset for y1 + y2 + cnt
    cudaMemsetAsync(ppool, 0, (size_t)(3 * NN + 1) * 4, 0);

    const int B = 256;
    const int G  = (NN + B - 1) / B;
    const int G4 = (NN / 4 + B - 1) / B;

    k_dst_scat1<<<G, B>>>(y_hat, df, (int*)pdst, y1);
    k_scat2<<<G, B>>>((const int*)pdst, y1, y2);
    k_colsum<<<G4, B>>>(y2, y1);                       // colsums into y1
    k_pool_erode<<<G, B>>>(y1, (unsigned char*)pmask, (int*)ppar);
    k_union<<<G, B>>>((const unsigned char*)pmask, (int*)ppar);
    k_flatten<<<G, B>>>((const unsigned char*)pmask, (int*)ppar, (int*)plab);
    k_labi<<<G, B>>>(y_hat, (const int*)pdst, (const int*)plab, (int*)plabi, cnt);
    k_final<<<G4, B>>>((const int*)plabi, cnt, out);
}

// round 6
// speedup vs baseline: 13.8884x; 1.0451x over previous
#include <cuda_runtime.h>

#define HH 1024
#define WW 1536
#define NN (HH*WW)

// ---------------- device scratch (no allocation allowed) ----------------
// pooled zero-init region: [0,NN)=y1 ; [NN,2NN)=y2 ; [2NN,3NN+1)=cnt
static __device__ int g_pool[3 * NN + 1];
static __device__ int g_dst[NN];
static __device__ unsigned char g_mask[NN];
static __device__ int g_par[NN];
static __device__ int g_labi[NN];

// ---------------- kernels ----------------

// dst_ids + first scatter fused
__global__ void k_dst_scat1(const float* __restrict__ yh, const float* __restrict__ df,
                            int* __restrict__ dst, int* __restrict__ y1) {
    int i = blockIdx.x * blockDim.x + threadIdx.x;
    if (i >= NN) return;
    float dx = df[i];
    float dy = df[NN + i];
    float l2  = __fadd_rn(__fmul_rn(dx, dx), __fmul_rn(dy, dy));
    float len = __fsqrt_rn(l2);
    float den = __fadd_rn(len, 1e-19f);
    float ux  = __fdiv_rn(dx, den);
    float uy  = __fdiv_rn(dy, den);
    float dfc = fminf(fmaxf(len, 3.0f), 6.0f);
    int r = i / WW;
    int c = i - r * WW;
    float px = __fadd_rn((float)r, __fmul_rn(ux, dfc));
    float py = __fadd_rn((float)c, __fmul_rn(uy, dfc));
    px = fminf(fmaxf(px, 0.0f), (float)(HH - 1));
    py = fminf(fmaxf(py, 0.0f), (float)(WW - 1));
    int d = __float2int_rn(px) * WW + __float2int_rn(py);  // ties-to-even
    dst[i] = d;
    if (yh[i] > 0.5f) atomicAdd(&y1[d], 1);
}

// y2[dst[i]] += y1[i]
__global__ void k_scat2(const int* __restrict__ dst, const int* __restrict__ y1,
                        int* __restrict__ y2) {
    int i = blockIdx.x * blockDim.x + threadIdx.x;
    if (i >= NN) return;
    int v = y1[i];
    if (v) atomicAdd(&y2[dst[i]], v);
}

// ---- fused avgpool5 (count_include_pad=False) + threshold + cross-erosion ----
// Tile 32x8 px. smem: y2 (14x38), colsum (10x38), m0 (10x36; computed once).
// m0 outside the image = foreground (reference pads with True).
#define TW 32
#define TH 8
__global__ void k_pool_erode(const int* __restrict__ y2,
                             unsigned char* __restrict__ mask,
                             int* __restrict__ par) {
    __shared__ int y2s[14][38];
    __shared__ int css[10][38];
    __shared__ unsigned char m0s[10][36];

    int tx = threadIdx.x, ty = threadIdx.y;
    int tid = ty * TW + tx;
    int gr0 = blockIdx.y * TH;     // tile origin
    int gc0 = blockIdx.x * TW;

    // stage y2 rows gr0-3..gr0+10, cols gc0-3..gc0+34 (zeros outside)
    for (int k = tid; k < 14 * 38; k += TW * TH) {
        int rr = k / 38, cc = k % 38;
        int gr = gr0 - 3 + rr, gc = gc0 - 3 + cc;
        y2s[rr][cc] = (gr >= 0 && gr < HH && gc >= 0 && gc < WW) ? y2[gr * WW + gc] : 0;
    }
    __syncthreads();

    // vertical 5-sums: cs row k corresponds to image row gr0-1+k
    for (int k = tid; k < 10 * 38; k += TW * TH) {
        int rr = k / 38, cc = k % 38;
        css[rr][cc] = y2s[rr][cc] + y2s[rr + 1][cc] + y2s[rr + 2][cc]
                    + y2s[rr + 3][cc] + y2s[rr + 4][cc];
    }
    __syncthreads();

    // m0: row k -> image row gr0-1+k ; col j -> image col gc0-1+j
    for (int k = tid; k < 10 * 34; k += TW * TH) {
        int rr = k / 34, jj = k % 34;
        int r = gr0 - 1 + rr, c = gc0 - 1 + jj;
        unsigned char m;
        if (r < 0 || r >= HH || c < 0 || c >= WW) {
            m = 1;                                   // pad = foreground
        } else {
            int s = css[rr][jj] + css[rr][jj + 1] + css[rr][jj + 2]
                  + css[rr][jj + 3] + css[rr][jj + 4];
            int rin = min(r + 2, HH - 1) - max(r - 2, 0) + 1;
            int cin = min(c + 2, WW - 1) - max(c - 2, 0) + 1;
            m = (unsigned char)(2 * s >= rin * cin);
        }
        m0s[rr][jj] = m;
    }
    __syncthreads();

    // cross erosion; thread pixel at m0s[ty+1][tx+1]
    int r = gr0 + ty, c = gc0 + tx;
    unsigned char m = m0s[ty + 1][tx + 1] & m0s[ty][tx + 1] & m0s[ty + 2][tx + 1]
                    & m0s[ty + 1][tx] & m0s[ty + 1][tx + 2];
    int i = r * WW + c;
    mask[i] = m;
    par[i] = i;
}

__device__ __forceinline__ int uf_find(int* __restrict__ par, int i) {
    int p = par[i];
    while (p != par[p]) p = par[p];
    return p;
}

// lock-free union: hook smaller root under larger root
// -> final root of a component == max linear index (reference's label)
__device__ void uf_union(int* __restrict__ par, int a, int b) {
    while (true) {
        a = uf_find(par, a);
        b = uf_find(par, b);
        if (a == b) return;
        int hi = max(a, b);
        int lo = min(a, b);
        int old = atomicCAS(&par[lo], lo, hi);
        if (old == lo) return;
        a = hi; b = old;
    }
}

// union each mask pixel with E, SW, S, SE mask neighbors (covers 8-conn)
__global__ void k_union(const unsigned char* __restrict__ mask, int* __restrict__ par) {
    int i = blockIdx.x * blockDim.x + threadIdx.x;
    if (i >= NN) return;
    if (!mask[i]) return;
    int r = i / WW;
    int c = i - r * WW;
    if (c < WW - 1 && mask[i + 1]) uf_union(par, i, i + 1);
    if (r < HH - 1) {
        if (mask[i + WW]) uf_union(par, i, i + WW);
        if (c > 0      && mask[i + WW - 1]) uf_union(par, i, i + WW - 1);
        if (c < WW - 1 && mask[i + WW + 1]) uf_union(par, i, i + WW + 1);
    }
}

// inst = label(dst^8(i)) * fore ; warp-aggregated per-label histogram
__global__ void k_labi(const float* __restrict__ yh, const int* __restrict__ dst,
                       const unsigned char* __restrict__ mask, int* __restrict__ par,
                       int* __restrict__ labi, int* __restrict__ cnt) {
    int i = blockIdx.x * blockDim.x + threadIdx.x;   // grid exact: NN % 256 == 0
    int la = 0;
    if (yh[i] > 0.5f) {
        int j = i;
#pragma unroll
        for (int h = 0; h < 8; h++) j = dst[j];
        if (mask[j]) la = uf_find(par, j) + 1;
    }
    labi[i] = la;
    // one atomic per distinct label per warp
    unsigned peers = __match_any_sync(0xffffffffu, la);
    int lane = threadIdx.x & 31;
    if (la > 0 && (__ffs(peers) - 1) == lane)
        atomicAdd(&cnt[la], __popc(peers));
}

// keep components with size > 256; value = label (segment_max(L)==L exactly)
__global__ void k_final(const int* __restrict__ labi, const int* __restrict__ cnt,
                        float* __restrict__ out) {
    int q = blockIdx.x * blockDim.x + threadIdx.x;
    if (q >= NN / 4) return;
    int i = q * 4;
    int4 la = *(const int4*)(labi + i);
    float4 o;
    o.x = (la.x > 0 && cnt[la.x] > 256) ? (float)la.x : 0.0f;
    o.y = (la.y > 0 && cnt[la.y] > 256) ? (float)la.y : 0.0f;
    o.z = (la.z > 0 && cnt[la.z] > 256) ? (float)la.z : 0.0f;
    o.w = (la.w > 0 && cnt[la.w] > 256) ? (float)la.w : 0.0f;
    *(float4*)(out + i) = o;
}

// ---------------- launcher ----------------
extern "C" void kernel_launch(void* const* d_in, const int* in_sizes, int n_in,
                              void* d_out, int out_size) {
    const float* y_hat;
    const float* df;
    if (in_sizes[0] == NN) { y_hat = (const float*)d_in[0]; df = (const float*)d_in[1]; }
    else                   { df = (const float*)d_in[0]; y_hat = (const float*)d_in[1]; }
    float* out = (float*)d_out;

    void *ppool, *pdst, *pmask, *ppar, *plabi;
    cudaGetSymbolAddress(&ppool, g_pool);
    cudaGetSymbolAddress(&pdst, g_dst);
    cudaGetSymbolAddress(&pmask, g_mask);
    cudaGetSymbolAddress(&ppar, g_par);
    cudaGetSymbolAddress(&plabi, g_labi);

    int* y1  = (int*)ppool;
    int* y2  = y1 + NN;
    int* cnt = y1 + 2 * NN;

    cudaMemsetAsync(ppool, 0, (size_t)(3 * NN + 1) * 4, 0);

    const int B = 256;
    const int G  = (NN + B - 1) / B;
    const int G4 = (NN / 4 + B - 1) / B;

    k_dst_scat1<<<G, B>>>(y_hat, df, (int*)pdst, y1);
    k_scat2<<<G, B>>>((const int*)pdst, y1, y2);
    {
        dim3 blk(TW, TH);
        dim3 grd(WW / TW, HH / TH);
        k_pool_erode<<<grd, blk>>>(y2, (unsigned char*)pmask, (int*)ppar);
    }
    k_union<<<G, B>>>((const unsigned char*)pmask, (int*)ppar);
    k_labi<<<G, B>>>(y_hat, (const int*)pdst, (const unsigned char*)pmask,
                     (int*)ppar, (int*)plabi, cnt);
    k_final<<<G4, B>>>((const int*)plabi, cnt, out);
}

// round 10
// speedup vs baseline: 14.3295x; 1.0318x over previous
#include <cuda_runtime.h>

#define HH 1024
#define WW 1536
#define NN (HH*WW)

// ---------------- device scratch (no allocation allowed) ----------------
// pooled zero-init region: [0,NN)=y1 ; [NN,2NN)=y2 ; [2NN,3NN+1)=cnt
static __device__ int g_pool[3 * NN + 1];
static __device__ int g_dst[NN];
static __device__ unsigned char g_mask[NN];
static __device__ int g_par[NN];
static __device__ int g_labi[NN];

// ---------------- kernels ----------------

// dst_ids + first scatter fused; 4 px/thread (float4 plane loads)
__global__ void k_dst_scat1(const float* __restrict__ yh, const float* __restrict__ df,
                            int* __restrict__ dst, int* __restrict__ y1) {
    int q = blockIdx.x * blockDim.x + threadIdx.x;
    if (q >= NN / 4) return;
    int i = q * 4;
    float4 vx = *(const float4*)(df + i);
    float4 vy = *(const float4*)(df + NN + i);
    float4 vh = *(const float4*)(yh + i);
    int r = i / WW;                       // WW%4==0 -> same row for all 4
    int c = i - r * WW;
    int4 d;
    float dxs[4] = {vx.x, vx.y, vx.z, vx.w};
    float dys[4] = {vy.x, vy.y, vy.z, vy.w};
    int   ds[4];
#pragma unroll
    for (int k = 0; k < 4; k++) {
        float dx = dxs[k], dy = dys[k];
        float l2  = __fadd_rn(__fmul_rn(dx, dx), __fmul_rn(dy, dy));
        float len = __fsqrt_rn(l2);
        float den = __fadd_rn(len, 1e-19f);
        float ux  = __fdiv_rn(dx, den);
        float uy  = __fdiv_rn(dy, den);
        float dfc = fminf(fmaxf(len, 3.0f), 6.0f);
        float px = __fadd_rn((float)r, __fmul_rn(ux, dfc));
        float py = __fadd_rn((float)(c + k), __fmul_rn(uy, dfc));
        px = fminf(fmaxf(px, 0.0f), (float)(HH - 1));
        py = fminf(fmaxf(py, 0.0f), (float)(WW - 1));
        ds[k] = __float2int_rn(px) * WW + __float2int_rn(py);  // ties-to-even
    }
    d.x = ds[0]; d.y = ds[1]; d.z = ds[2]; d.w = ds[3];
    *(int4*)(dst + i) = d;
    if (vh.x > 0.5f) atomicAdd(&y1[d.x], 1);
    if (vh.y > 0.5f) atomicAdd(&y1[d.y], 1);
    if (vh.z > 0.5f) atomicAdd(&y1[d.z], 1);
    if (vh.w > 0.5f) atomicAdd(&y1[d.w], 1);
}

// y2[dst[i]] += y1[i]; 4 px/thread
__global__ void k_scat2(const int* __restrict__ dst, const int* __restrict__ y1,
                        int* __restrict__ y2) {
    int q = blockIdx.x * blockDim.x + threadIdx.x;
    if (q >= NN / 4) return;
    int i = q * 4;
    int4 v = *(const int4*)(y1 + i);
    if (v.x | v.y | v.z | v.w) {
        int4 d = *(const int4*)(dst + i);
        if (v.x) atomicAdd(&y2[d.x], v.x);
        if (v.y) atomicAdd(&y2[d.y], v.y);
        if (v.z) atomicAdd(&y2[d.z], v.z);
        if (v.w) atomicAdd(&y2[d.w], v.w);
    }
}

// ---- fused avgpool5(count_include_pad=False) + threshold + cross-erosion
//      + union-find parent init (par[i] = largest masked forward neighbor) ----
#define TW 32
#define TH 8
__global__ void k_pool_erode(const int* __restrict__ y2,
                             unsigned char* __restrict__ mask,
                             int* __restrict__ par) {
    __shared__ int y2s[16][40];            // rows gr0-4..gr0+11, cols gc0-4..gc0+35
    __shared__ int css[12][40];            // row k ~ image row gr0-2+k
    __shared__ unsigned char m0s[12][36];  // (k,j) ~ (gr0-2+k, gc0-2+j); OOB = 1
    __shared__ unsigned char mes[10][34];  // eroded; (k,j) ~ (gr0-1+k, gc0-1+j); OOB = 0

    int tx = threadIdx.x, ty = threadIdx.y;
    int tid = ty * TW + tx;
    int gr0 = blockIdx.y * TH;
    int gc0 = blockIdx.x * TW;

    for (int k = tid; k < 16 * 40; k += TW * TH) {
        int rr = k / 40, cc = k % 40;
        int gr = gr0 - 4 + rr, gc = gc0 - 4 + cc;
        y2s[rr][cc] = (gr >= 0 && gr < HH && gc >= 0 && gc < WW) ? y2[gr * WW + gc] : 0;
    }
    __syncthreads();

    for (int k = tid; k < 12 * 40; k += TW * TH) {
        int rr = k / 40, cc = k % 40;
        css[rr][cc] = y2s[rr][cc] + y2s[rr + 1][cc] + y2s[rr + 2][cc]
                    + y2s[rr + 3][cc] + y2s[rr + 4][cc];
    }
    __syncthreads();

    for (int k = tid; k < 12 * 36; k += TW * TH) {
        int rr = k / 36, jj = k % 36;
        int r = gr0 - 2 + rr, c = gc0 - 2 + jj;
        unsigned char m;
        if (r < 0 || r >= HH || c < 0 || c >= WW) {
            m = 1;                                   // pad = foreground
        } else {
            int s = css[rr][jj] + css[rr][jj + 1] + css[rr][jj + 2]
                  + css[rr][jj + 3] + css[rr][jj + 4];
            int rin = min(r + 2, HH - 1) - max(r - 2, 0) + 1;
            int cin = min(c + 2, WW - 1) - max(c - 2, 0) + 1;
            m = (unsigned char)(2 * s >= rin * cin);
        }
        m0s[rr][jj] = m;
    }
    __syncthreads();

    for (int k = tid; k < 10 * 34; k += TW * TH) {
        int rr = k / 34, jj = k % 34;
        int r = gr0 - 1 + rr, c = gc0 - 1 + jj;
        unsigned char m = 0;
        if (r >= 0 && r < HH && c >= 0 && c < WW) {
            m = m0s[rr + 1][jj + 1] & m0s[rr][jj + 1] & m0s[rr + 2][jj + 1]
              & m0s[rr + 1][jj] & m0s[rr + 1][jj + 2];
        }
        mes[rr][jj] = m;
    }
    __syncthreads();

    // thread pixel at mes[ty+1][tx+1]; forward neighbors: SE > S > SW > E
    int r = gr0 + ty, c = gc0 + tx;
    int i = r * WW + c;
    unsigned char m = mes[ty + 1][tx + 1];
    int p = i;
    if (m) {
        if      (mes[ty + 2][tx + 2]) p = i + WW + 1;
        else if (mes[ty + 2][tx + 1]) p = i + WW;
        else if (mes[ty + 2][tx])     p = i + WW - 1;
        else if (mes[ty + 1][tx + 2]) p = i + 1;
    }
    mask[i] = m;
    par[i] = p;
}

// find with path halving (parents are strictly increasing -> no ABA)
__device__ __forceinline__ int uf_find(int* __restrict__ par, int i) {
    int p = par[i];
    while (true) {
        int pp = par[p];
        if (p == pp) return p;
        par[i] = pp;          // halving: install grandparent (a valid ancestor)
        i = p; p = pp;
    }
}

// lock-free union: hook smaller root under larger root
// -> final root of a component == max linear index (reference's label)
__device__ void uf_union(int* __restrict__ par, int a, int b) {
    while (true) {
        a = uf_find(par, a);
        b = uf_find(par, b);
        if (a == b) return;
        int hi = max(a, b);
        int lo = min(a, b);
        int old = atomicCAS(&par[lo], lo, hi);
        if (old == lo) return;
        a = hi; b = old;
    }
}

// union each mask pixel with E, SW, S, SE mask neighbors (covers 8-conn)
__global__ void k_union(const unsigned char* __restrict__ mask, int* __restrict__ par) {
    int i = blockIdx.x * blockDim.x + threadIdx.x;
    if (i >= NN) return;
    if (!mask[i]) return;
    int r = i / WW;
    int c = i - r * WW;
    if (c < WW - 1 && mask[i + 1]) uf_union(par, i, i + 1);
    if (r < HH - 1) {
        if (mask[i + WW]) uf_union(par, i, i + WW);
        if (c > 0      && mask[i + WW - 1]) uf_union(par, i, i + WW - 1);
        if (c < WW - 1 && mask[i + WW + 1]) uf_union(par, i, i + WW + 1);
    }
}

// inst = label(dst^8(i)) * fore ; warp-aggregated per-label histogram
__global__ void k_labi(const float* __restrict__ yh, const int* __restrict__ dst,
                       const unsigned char* __restrict__ mask, int* __restrict__ par,
                       int* __restrict__ labi, int* __restrict__ cnt) {
    int i = blockIdx.x * blockDim.x + threadIdx.x;   // grid exact: NN % 256 == 0
    int la = 0;
    if (yh[i] > 0.5f) {
        int j = i;
#pragma unroll
        for (int h = 0; h < 8; h++) j = dst[j];
        if (mask[j]) la = uf_find(par, j) + 1;
    }
    labi[i] = la;
    // one atomic per distinct label per warp
    unsigned peers = __match_any_sync(0xffffffffu, la);
    int lane = threadIdx.x & 31;
    if (la > 0 && (__ffs(peers) - 1) == lane)
        atomicAdd(&cnt[la], __popc(peers));
}

// keep components with size > 256; value = label (segment_max(L)==L exactly)
__global__ void k_final(const int* __restrict__ labi, const int* __restrict__ cnt,
                        float* __restrict__ out) {
    int q = blockIdx.x * blockDim.x + threadIdx.x;
    if (q >= NN / 4) return;
    int i = q * 4;
    int4 la = *(const int4*)(labi + i);
    float4 o;
    o.x = (la.x > 0 && cnt[la.x] > 256) ? (float)la.x : 0.0f;
    o.y = (la.y > 0 && cnt[la.y] > 256) ? (float)la.y : 0.0f;
    o.z = (la.z > 0 && cnt[la.z] > 256) ? (float)la.z : 0.0f;
    o.w = (la.w > 0 && cnt[la.w] > 256) ? (float)la.w : 0.0f;
    *(float4*)(out + i) = o;
}

// ---------------- launcher ----------------
extern "C" void kernel_launch(void* const* d_in, const int* in_sizes, int n_in,
                              void* d_out, int out_size) {
    const float* y_hat;
    const float* df;
    if (in_sizes[0] == NN) { y_hat = (const float*)d_in[0]; df = (const float*)d_in[1]; }
    else                   { df = (const float*)d_in[0]; y_hat = (const float*)d_in[1]; }
    float* out = (float*)d_out;

    void *ppool, *pdst, *pmask, *ppar, *plabi;
    cudaGetSymbolAddress(&ppool, g_pool);
    cudaGetSymbolAddress(&pdst, g_dst);
    cudaGetSymbolAddress(&pmask, g_mask);
    cudaGetSymbolAddress(&ppar, g_par);
    cudaGetSymbolAddress(&plabi, g_labi);

    int* y1  = (int*)ppool;
    int* y2  = y1 + NN;
    int* cnt = y1 + 2 * NN;

    cudaMemsetAsync(ppool, 0, (size_t)(3 * NN + 1) * 4, 0);

    const int B = 256;
    const int G  = (NN + B - 1) / B;
    const int G4 = (NN / 4 + B - 1) / B;

    k_dst_scat1<<<G4, B>>>(y_hat, df, (int*)pdst, y1);
    k_scat2<<<G4, B>>>((const int*)pdst, y1, y2);
    {
        dim3 blk(TW, TH);
        dim3 grd(WW / TW, HH / TH);
        k_pool_erode<<<grd, blk>>>(y2, (unsigned char*)pmask, (int*)ppar);
    }
    k_union<<<G, B>>>((const unsigned char*)pmask, (int*)ppar);
    k_labi<<<G, B>>>(y_hat, (const int*)pdst, (const unsigned char*)pmask,
                     (int*)ppar, (int*)plabi, cnt);
    k_final<<<G4, B>>>((const int*)plabi, cnt, out);
}